// round 12
// baseline (speedup 1.0000x reference)
#include <cuda_runtime.h>
#include <cstdint>

#define BB 256
#define TT 512
#define II 64
#define HH 512
#define OO 24

#define CLUSTER_NCTAS 8
#define NBLOCKS 128
#define NTHREADS 512

#define BM 16     // batch rows per cluster
#define HC 64     // hidden cols per CTA (rank)

typedef unsigned long long u64;

// SMEM floats: Wk 128KB + Wi 16KB + Hs 32KB + Xs 4KB
#define WK_FLOATS 32768
#define WI_FLOATS 4096
#define HS_FLOATS 8192
#define XS_FLOATS 1024
#define SMEM_BYTES ((WK_FLOATS + WI_FLOATS + HS_FLOATS + XS_FLOATS) * 4) // 184320

// Global h exchange, layout identical to smem Hs: f2[k2][b] (k-pair major)
__device__ float2 g_h2[2][(HH / 2) * BB];

#define FFMA2(acc, a, w) \
    asm("fma.rn.f32x2 %0, %1, %2, %0;" : "+l"(acc) : "l"(a), "l"(w))

__device__ __forceinline__ float4 ld_cg_v4(const float4* p) {
    float4 v;
    asm volatile("ld.global.cg.v4.f32 {%0,%1,%2,%3}, [%4];"
                 : "=f"(v.x), "=f"(v.y), "=f"(v.z), "=f"(v.w) : "l"(p) : "memory");
    return v;
}
__device__ __forceinline__ float2 ld_cg_v2(const float2* p) {
    float2 v;
    asm volatile("ld.global.cg.v2.f32 {%0,%1}, [%2];"
                 : "=f"(v.x), "=f"(v.y) : "l"(p) : "memory");
    return v;
}

__global__ void __launch_bounds__(NTHREADS, 1) __cluster_dims__(CLUSTER_NCTAS, 1, 1)
rnn_persistent_kernel(const float* __restrict__ x,
                      const float* __restrict__ W_ih,
                      const float* __restrict__ W_hh,
                      const float* __restrict__ b_ih,
                      const float* __restrict__ b_hh,
                      const float* __restrict__ fc_w,
                      const float* __restrict__ fc_b,
                      float* __restrict__ out)
{
    extern __shared__ float smem[];
    float* Wk = smem;                     // [k2:256][c2:32] float4, kh-swizzled
    float* Wi = smem + WK_FLOATS;         // [i2:32][c2:32] float4, kh-swizzled
    float* Hs = Wi + WI_FLOATS;           // [k2:256][b:16] float2
    float* Xs = Hs + HS_FLOATS;           // [i2:32][b:16]  float2

    const int tid  = threadIdx.x;
    const int lane = tid & 31;
    const int warp = tid >> 5;            // 0..15
    const int rank = blockIdx.x & (CLUSTER_NCTAS - 1);
    const int cl   = blockIdx.x >> 3;
    const int b0   = cl * BM;
    const int h0   = rank * HC;
    const int hw   = h0 + 4 * warp;       // warp's 4 h-columns
    const int kh   = lane >> 4;           // k-half this lane sums
    const int bl   = lane & 15;           // batch row this lane owns

    // ---- one-time weight staging (STS conflict-free: c2 in lanes) ----
    for (int n = 0; n < 16; ++n) {
        int idx = tid + n * NTHREADS;     // 0..8191
        int c2 = idx & 31, k2 = idx >> 5; // c2 0..31, k2 0..255
        float2 wa = *(const float2*)&W_hh[(size_t)(h0 + 2 * c2) * HH + 2 * k2];
        float2 wb = *(const float2*)&W_hh[(size_t)(h0 + 2 * c2 + 1) * HH + 2 * k2];
        uint32_t off = (uint32_t)(k2 * 512 + c2 * 16) ^ (uint32_t)((k2 & 128) >> 1);
        *(float4*)((char*)Wk + off) = make_float4(wa.x, wa.y, wb.x, wb.y);
    }
    for (int n = 0; n < 2; ++n) {
        int idx = tid + n * NTHREADS;     // 0..1023
        int c2 = idx & 31, i2 = idx >> 5; // i2 0..31
        float2 wa = *(const float2*)&W_ih[(size_t)(h0 + 2 * c2) * II + 2 * i2];
        float2 wb = *(const float2*)&W_ih[(size_t)(h0 + 2 * c2 + 1) * II + 2 * i2];
        uint32_t off = (uint32_t)(i2 * 512 + c2 * 16) ^ (uint32_t)((i2 & 16) << 2);
        *(float4*)((char*)Wi + off) = make_float4(wa.x, wa.y, wb.x, wb.y);
    }
    const float bias0 = b_ih[hw + 0] + b_hh[hw + 0];
    const float bias1 = b_ih[hw + 1] + b_hh[hw + 1];
    const float bias2 = b_ih[hw + 2] + b_hh[hw + 2];
    const float bias3 = b_ih[hw + 3] + b_hh[hw + 3];

    // ---- hot-loop base pointers (all increments are compile-time imm) ----
    const char* aB  = (const char*)Hs + kh * 16384 + bl * 8;   // Hs[128*kh][bl]
    const char* xB  = (const char*)Xs + kh * 2048  + bl * 8;   // Xs[16*kh][bl]
    const char* wkB = (const char*)Wk + kh * 65536
                      + ((uint32_t)(2 * warp * 16) ^ (uint32_t)(kh * 64));
    const char* wiB = (const char*)Wi + kh * 8192
                      + ((uint32_t)(2 * warp * 16) ^ (uint32_t)(kh * 64));

    // this rank's k2 base in the global h layout
    const int k2g = rank * (HC / 2) + 2 * warp;   // rank*32 + 2*warp

    const float4* x4 = (const float4*)x;
    const int xb  = tid >> 4;             // batch row (tid<256)
    const int xi4 = tid & 15;
    float4 xreg;
    if (tid < 256)
        xreg = x4[((size_t)(b0 + xb) * TT + 0) * 16 + xi4];

    for (int t = 0; t < TT; ++t) {
        const float2* gprev = g_h2[1 - (t & 1)];
        float2*       gnew  = g_h2[t & 1];

        // ---- commit x_t: Xs[2*xi4][xb], Xs[2*xi4+1][xb] ----
        if (tid < 256) {
            ((float2*)Xs)[(2 * xi4) * BM + xb]     = make_float2(xreg.x, xreg.y);
            ((float2*)Xs)[(2 * xi4 + 1) * BM + xb] = make_float2(xreg.z, xreg.w);
        }
        // ---- restage h_{t-1}: full 32KB tile (256 k2 x 8 float4) ----
        if (t > 0) {
            #pragma unroll
            for (int n = 0; n < 4; ++n) {
                int u = tid + n * NTHREADS;          // 0..2047
                int k2 = u >> 3, bq = u & 7;         // 8 float4 per k2 row
                float4 v = ld_cg_v4(
                    (const float4*)(gprev + (size_t)k2 * BB + b0) + bq);
                ((float4*)Hs)[u] = v;
            }
        }
        __syncthreads();

        u64 acc0 = 0ull, acc1 = 0ull, acc2 = 0ull, acc3 = 0ull;

        // ---- input projection: 16 i-pair iters (lane's kh half) ----
        {
            const char* ap = xB;
            const char* wp = wiB;
            #pragma unroll
            for (int i = 0; i < 16; ++i) {
                u64 a = *(const u64*)ap;
                ulonglong2 wA = *(const ulonglong2*)wp;
                ulonglong2 wB = *(const ulonglong2*)(wp + 16);
                FFMA2(acc0, a, wA.x);
                FFMA2(acc1, a, wA.y);
                FFMA2(acc2, a, wB.x);
                FFMA2(acc3, a, wB.y);
                ap += 128; wp += 512;
            }
        }
        // ---- recurrent projection: 128 k-pair iters ----
        if (t > 0) {
            const char* ap = aB;
            const char* wp = wkB;
            #pragma unroll 16
            for (int i = 0; i < 128; ++i) {
                u64 a = *(const u64*)ap;
                ulonglong2 wA = *(const ulonglong2*)wp;
                ulonglong2 wB = *(const ulonglong2*)(wp + 16);
                FFMA2(acc0, a, wA.x);
                FFMA2(acc1, a, wA.y);
                FFMA2(acc2, a, wB.x);
                FFMA2(acc3, a, wB.y);
                ap += 128; wp += 512;
            }
        }

        // ---- combine (even,odd) halves + kh pair, bias, relu ----
        float s0, s1, s2, s3, e;
        asm("mov.b64 {%0,%1}, %2;" : "=f"(s0), "=f"(e) : "l"(acc0)); s0 += e;
        asm("mov.b64 {%0,%1}, %2;" : "=f"(s1), "=f"(e) : "l"(acc1)); s1 += e;
        asm("mov.b64 {%0,%1}, %2;" : "=f"(s2), "=f"(e) : "l"(acc2)); s2 += e;
        asm("mov.b64 {%0,%1}, %2;" : "=f"(s3), "=f"(e) : "l"(acc3)); s3 += e;
        s0 += __shfl_xor_sync(0xffffffffu, s0, 16);
        s1 += __shfl_xor_sync(0xffffffffu, s1, 16);
        s2 += __shfl_xor_sync(0xffffffffu, s2, 16);
        s3 += __shfl_xor_sync(0xffffffffu, s3, 16);

        if (kh == 0) {
            float v0 = fmaxf(s0 + bias0, 0.f);
            float v1 = fmaxf(s1 + bias1, 0.f);
            float v2 = fmaxf(s2 + bias2, 0.f);
            float v3 = fmaxf(s3 + bias3, 0.f);
            // h_t cols hw..hw+3 for batch bl -> g_h2[k2g..k2g+1][b0+bl]
            gnew[(size_t)(k2g)     * BB + b0 + bl] = make_float2(v0, v1);
            gnew[(size_t)(k2g + 1) * BB + b0 + bl] = make_float2(v2, v3);
        }

        // ---- prefetch x_{t+1} (hides under barrier) ----
        if (tid < 256 && t + 1 < TT)
            xreg = x4[((size_t)(b0 + xb) * TT + (t + 1)) * 16 + xi4];

        // ---- cluster barrier: release h stores, acquire peers' ----
        asm volatile("fence.acq_rel.cluster;" ::: "memory");
        asm volatile("barrier.cluster.arrive.aligned;" ::: "memory");
        asm volatile("barrier.cluster.wait.aligned;"   ::: "memory");
    }

    // ---- fused FC epilogue: warp handles batch row b0+warp ----
    {
        const float2* hT = g_h2[(TT - 1) & 1];
        float2 hp[8];
        #pragma unroll
        for (int i = 0; i < 8; ++i)
            hp[i] = ld_cg_v2(&hT[(size_t)(lane + 32 * i) * BB + b0 + warp]);
        #pragma unroll
        for (int oo = 0; oo < OO / CLUSTER_NCTAS; ++oo) {
            int o = rank * (OO / CLUSTER_NCTAS) + oo;
            const float2* w2 = (const float2*)(fc_w + (size_t)o * HH);
            float s = 0.f;
            #pragma unroll
            for (int i = 0; i < 8; ++i) {
                float2 wv = w2[lane + 32 * i];
                s = fmaf(hp[i].x, wv.x, s);
                s = fmaf(hp[i].y, wv.y, s);
            }
            #pragma unroll
            for (int d = 16; d > 0; d >>= 1)
                s += __shfl_xor_sync(0xffffffffu, s, d);
            if (lane == 0)
                out[(size_t)(b0 + warp) * OO + o] = s + fc_b[o];
        }
    }
}

extern "C" void kernel_launch(void* const* d_in, const int* in_sizes, int n_in,
                              void* d_out, int out_size)
{
    const float* x    = (const float*)d_in[0];
    const float* W_ih = (const float*)d_in[1];
    const float* W_hh = (const float*)d_in[2];
    const float* b_ih = (const float*)d_in[3];
    const float* b_hh = (const float*)d_in[4];
    const float* fc_w = (const float*)d_in[5];
    const float* fc_b = (const float*)d_in[6];
    int nb = 0;
    for (int i = 0; i < n_in; ++i) {
        const float* p = (const float*)d_in[i];
        switch (in_sizes[i]) {
            case BB * TT * II: x    = p; break;
            case HH * II:      W_ih = p; break;
            case HH * HH:      W_hh = p; break;
            case OO * HH:      fc_w = p; break;
            case OO:           fc_b = p; break;
            case HH:           if (nb++ == 0) b_ih = p; else b_hh = p; break;
            default: break;
        }
    }
    float* out = (float*)d_out;

    cudaFuncSetAttribute(rnn_persistent_kernel,
                         cudaFuncAttributeMaxDynamicSharedMemorySize, SMEM_BYTES);
    rnn_persistent_kernel<<<NBLOCKS, NTHREADS, SMEM_BYTES>>>(
        x, W_ih, W_hh, b_ih, b_hh, fc_w, fc_b, out);
}

// round 13
// speedup vs baseline: 2.3435x; 2.3435x over previous
#include <cuda_runtime.h>
#include <cstdint>

#define BB 256
#define TT 512
#define II 64
#define HH 512
#define OO 24

#define CLUSTER_NCTAS 8
#define NBLOCKS 128
#define NTHREADS 512

#define BM 16     // batch rows per cluster
#define HC 64     // hidden cols per CTA (rank)

typedef unsigned long long u64;

// Hidden state ping-pong, b-major: g_h[parity][b][h]
__device__ float g_h[2][BB * HH];

// SMEM: Hs[16][128 float4] swizzled (32KB) + Xs[16][64] (4KB)
#define HS_F4 (BM * 128)
#define XS_F  (BM * II)
#define SMEM_BYTES (HS_F4 * 16 + XS_F * 4)   // 36864

#define FFMA2(acc, a, w) \
    asm("fma.rn.f32x2 %0, %1, %2, %0;" : "+l"(acc) : "l"(a), "l"(w))

__device__ __forceinline__ float4 ld_cg_v4(const float4* p) {
    float4 v;
    asm volatile("ld.global.cg.v4.f32 {%0,%1,%2,%3}, [%4];"
                 : "=f"(v.x), "=f"(v.y), "=f"(v.z), "=f"(v.w) : "l"(p) : "memory");
    return v;
}

__global__ void __launch_bounds__(NTHREADS, 1) __cluster_dims__(CLUSTER_NCTAS, 1, 1)
rnn_persistent_kernel(const float* __restrict__ x,
                      const float* __restrict__ W_ih,
                      const float* __restrict__ W_hh,
                      const float* __restrict__ b_ih,
                      const float* __restrict__ b_hh,
                      const float* __restrict__ fc_w,
                      const float* __restrict__ fc_b,
                      float* __restrict__ out)
{
    extern __shared__ float smem[];
    float4* Hs4 = (float4*)smem;              // [b][128 f4], piece-swizzled
    float*  Xs  = smem + HS_F4 * 4;           // [b][64]
    const u64* xq = (const u64*)Xs;

    const int tid  = threadIdx.x;
    const int lane = tid & 31;
    const int warp = tid >> 5;                // 0..15
    const int rank = blockIdx.x & (CLUSTER_NCTAS - 1);
    const int cl   = blockIdx.x >> 3;
    const int b0   = cl * BM;
    const int h0   = rank * HC;
    const int hw   = h0 + 4 * warp;           // warp's 4 h-columns
    const int k0   = lane * 16;               // lane's k-chunk
    const int i0   = lane * 2;                // lane's i-pair

    // ---- register-resident weights (constant across all timesteps) ----
    u64 whh[4][8];
    u64 wih[4];
    #pragma unroll
    for (int h = 0; h < 4; ++h) {
        const ulonglong2* wrow =
            (const ulonglong2*)&W_hh[(size_t)(hw + h) * HH + k0];
        #pragma unroll
        for (int j = 0; j < 4; ++j) {
            ulonglong2 v = wrow[j];
            whh[h][2 * j]     = v.x;
            whh[h][2 * j + 1] = v.y;
        }
        wih[h] = *(const u64*)&W_ih[(size_t)(hw + h) * II + i0];
    }
    const int h_idx = 2 * (lane & 1) + ((lane >> 1) & 1);   // reduction output map
    const float biasv = b_ih[hw + h_idx] + b_hh[hw + h_idx];

    const float4* x4 = (const float4*)x;

    for (int t = 0; t < TT; ++t) {
        const float4* gprev4 = (const float4*)g_h[1 - (t & 1)];
        float*        gnew   = g_h[t & 1];

        // ---- stage x_t ----
        if (tid < 256) {
            int b = tid >> 4, i4 = tid & 15;
            ((float4*)Xs)[b * 16 + i4] =
                x4[((size_t)(b0 + b) * TT + t) * 16 + i4];
        }
        // ---- stage h_{t-1} (coalesced) into swizzled Hs ----
        if (t > 0) {
            #pragma unroll
            for (int n = 0; n < 4; ++n) {
                int idx = tid + n * NTHREADS;
                int b = idx >> 7, p = idx & 127;
                float4 v = ld_cg_v4(gprev4 + (size_t)(b0 + b) * 128 + p);
                Hs4[b * 128 + (p ^ ((p >> 3) & 3))] = v;
            }
        }
        __syncthreads();

        const bool rec = (t > 0);

        // ---- 8 dual-row passes: rows (bp, bp+8) interleaved for ILP ----
        #pragma unroll 2
        for (int bp = 0; bp < 8; ++bp) {
            u64 acc0 = 0ull, acc1 = 0ull, acc2 = 0ull, acc3 = 0ull;  // row bp
            u64 acc4 = 0ull, acc5 = 0ull, acc6 = 0ull, acc7 = 0ull;  // row bp+8

            // input projection (both rows)
            u64 axA = xq[bp * 32 + lane];
            u64 axB = xq[(bp + 8) * 32 + lane];
            FFMA2(acc0, axA, wih[0]);
            FFMA2(acc4, axB, wih[0]);
            FFMA2(acc1, axA, wih[1]);
            FFMA2(acc5, axB, wih[1]);
            FFMA2(acc2, axA, wih[2]);
            FFMA2(acc6, axB, wih[2]);
            FFMA2(acc3, axA, wih[3]);
            FFMA2(acc7, axB, wih[3]);

            // recurrent projection (both rows), swizzled conflict-free LDS.128
            if (rec) {
                const ulonglong2* hrA = (const ulonglong2*)(Hs4 + bp * 128);
                const ulonglong2* hrB = (const ulonglong2*)(Hs4 + (bp + 8) * 128);
                #pragma unroll
                for (int j = 0; j < 4; ++j) {
                    int sidx = (lane * 4 + j) ^ ((lane >> 1) & 3);
                    ulonglong2 vA = hrA[sidx];
                    ulonglong2 vB = hrB[sidx];
                    FFMA2(acc0, vA.x, whh[0][2 * j]);
                    FFMA2(acc4, vB.x, whh[0][2 * j]);
                    FFMA2(acc0, vA.y, whh[0][2 * j + 1]);
                    FFMA2(acc4, vB.y, whh[0][2 * j + 1]);
                    FFMA2(acc1, vA.x, whh[1][2 * j]);
                    FFMA2(acc5, vB.x, whh[1][2 * j]);
                    FFMA2(acc1, vA.y, whh[1][2 * j + 1]);
                    FFMA2(acc5, vB.y, whh[1][2 * j + 1]);
                    FFMA2(acc2, vA.x, whh[2][2 * j]);
                    FFMA2(acc6, vB.x, whh[2][2 * j]);
                    FFMA2(acc2, vA.y, whh[2][2 * j + 1]);
                    FFMA2(acc6, vB.y, whh[2][2 * j + 1]);
                    FFMA2(acc3, vA.x, whh[3][2 * j]);
                    FFMA2(acc7, vB.x, whh[3][2 * j]);
                    FFMA2(acc3, vA.y, whh[3][2 * j + 1]);
                    FFMA2(acc7, vB.y, whh[3][2 * j + 1]);
                }
            }

            // unpack both rows
            float s0, s1, s2, s3, u0, u1, u2, u3, e;
            asm("mov.b64 {%0,%1}, %2;" : "=f"(s0), "=f"(e) : "l"(acc0)); s0 += e;
            asm("mov.b64 {%0,%1}, %2;" : "=f"(s1), "=f"(e) : "l"(acc1)); s1 += e;
            asm("mov.b64 {%0,%1}, %2;" : "=f"(s2), "=f"(e) : "l"(acc2)); s2 += e;
            asm("mov.b64 {%0,%1}, %2;" : "=f"(s3), "=f"(e) : "l"(acc3)); s3 += e;
            asm("mov.b64 {%0,%1}, %2;" : "=f"(u0), "=f"(e) : "l"(acc4)); u0 += e;
            asm("mov.b64 {%0,%1}, %2;" : "=f"(u1), "=f"(e) : "l"(acc5)); u1 += e;
            asm("mov.b64 {%0,%1}, %2;" : "=f"(u2), "=f"(e) : "l"(acc6)); u2 += e;
            asm("mov.b64 {%0,%1}, %2;" : "=f"(u3), "=f"(e) : "l"(acc7)); u3 += e;

            // two independent 6-shfl trees (proven R6 mapping) — interleaved
            bool o1 = lane & 1;
            bool o2 = lane & 2;
            float kA0 = o1 ? s2 : s0, kA1 = o1 ? s3 : s1;
            float gA0 = o1 ? s0 : s2, gA1 = o1 ? s1 : s3;
            float kB0 = o1 ? u2 : u0, kB1 = o1 ? u3 : u1;
            float gB0 = o1 ? u0 : u2, gB1 = o1 ? u1 : u3;
            kA0 += __shfl_xor_sync(0xffffffffu, gA0, 1);
            kB0 += __shfl_xor_sync(0xffffffffu, gB0, 1);
            kA1 += __shfl_xor_sync(0xffffffffu, gA1, 1);
            kB1 += __shfl_xor_sync(0xffffffffu, gB1, 1);
            float kA = o2 ? kA1 : kA0, gA = o2 ? kA0 : kA1;
            float kB = o2 ? kB1 : kB0, gB = o2 ? kB0 : kB1;
            kA += __shfl_xor_sync(0xffffffffu, gA, 2);
            kB += __shfl_xor_sync(0xffffffffu, gB, 2);
            kA += __shfl_xor_sync(0xffffffffu, kA, 4);
            kB += __shfl_xor_sync(0xffffffffu, kB, 4);
            kA += __shfl_xor_sync(0xffffffffu, kA, 8);
            kB += __shfl_xor_sync(0xffffffffu, kB, 8);
            kA += __shfl_xor_sync(0xffffffffu, kA, 16);
            kB += __shfl_xor_sync(0xffffffffu, kB, 16);

            if (lane < 4) {
                gnew[(size_t)(b0 + bp) * HH + hw + h_idx] =
                    fmaxf(kA + biasv, 0.f);
                gnew[(size_t)(b0 + bp + 8) * HH + hw + h_idx] =
                    fmaxf(kB + biasv, 0.f);
            }
        }

        // ---- cluster barrier (release h stores; acquire peers') ----
        asm volatile("fence.acq_rel.cluster;" ::: "memory");
        asm volatile("barrier.cluster.arrive.aligned;" ::: "memory");
        asm volatile("barrier.cluster.wait.aligned;"   ::: "memory");
    }

    // ---- fused FC epilogue (proven R9) ----
    {
        const float4* gl4 = (const float4*)g_h[(TT - 1) & 1];
        #pragma unroll
        for (int n = 0; n < 4; ++n) {
            int idx = tid + n * NTHREADS;
            int b = idx >> 7, p = idx & 127;
            float4 v = ld_cg_v4(gl4 + (size_t)(b0 + b) * 128 + p);
            Hs4[b * 128 + (p ^ ((p >> 3) & 3))] = v;
        }
        __syncthreads();

        if (rank == 0) {
            float4 hp[4];
            #pragma unroll
            for (int i = 0; i < 4; ++i) {
                int p = lane + 32 * i;
                hp[i] = Hs4[warp * 128 + (p ^ ((p >> 3) & 3))];
            }
            #pragma unroll 4
            for (int o = 0; o < OO; ++o) {
                const float4* w4 = (const float4*)(fc_w + (size_t)o * HH);
                float s = 0.f;
                #pragma unroll
                for (int i = 0; i < 4; ++i) {
                    float4 wv = __ldg(&w4[lane + 32 * i]);
                    s = fmaf(hp[i].x, wv.x, s);
                    s = fmaf(hp[i].y, wv.y, s);
                    s = fmaf(hp[i].z, wv.z, s);
                    s = fmaf(hp[i].w, wv.w, s);
                }
                #pragma unroll
                for (int d = 16; d > 0; d >>= 1)
                    s += __shfl_xor_sync(0xffffffffu, s, d);
                if (lane == 0)
                    out[(size_t)(b0 + warp) * OO + o] = s + fc_b[o];
            }
        }
    }
}

extern "C" void kernel_launch(void* const* d_in, const int* in_sizes, int n_in,
                              void* d_out, int out_size)
{
    const float* x    = (const float*)d_in[0];
    const float* W_ih = (const float*)d_in[1];
    const float* W_hh = (const float*)d_in[2];
    const float* b_ih = (const float*)d_in[3];
    const float* b_hh = (const float*)d_in[4];
    const float* fc_w = (const float*)d_in[5];
    const float* fc_b = (const float*)d_in[6];
    int nb = 0;
    for (int i = 0; i < n_in; ++i) {
        const float* p = (const float*)d_in[i];
        switch (in_sizes[i]) {
            case BB * TT * II: x    = p; break;
            case HH * II:      W_ih = p; break;
            case HH * HH:      W_hh = p; break;
            case OO * HH:      fc_w = p; break;
            case OO:           fc_b = p; break;
            case HH:           if (nb++ == 0) b_ih = p; else b_hh = p; break;
            default: break;
        }
    }
    float* out = (float*)d_out;

    cudaFuncSetAttribute(rnn_persistent_kernel,
                         cudaFuncAttributeMaxDynamicSharedMemorySize, SMEM_BYTES);
    rnn_persistent_kernel<<<NBLOCKS, NTHREADS, SMEM_BYTES>>>(
        x, W_ih, W_hh, b_ih, b_hh, fc_w, fc_b, out);
}